// round 4
// baseline (speedup 1.0000x reference)
#include <cuda_runtime.h>
#include <cstdint>

// NT=32, HS=64, WS=64 (K of qkv GEMM), CL=96, OD=128, G=8
// b = nt*64 + hs in [0,2048)

__device__ __align__(16) float g_scratch[2048 * 64 * 96];  // scr[b*6144 + d*96 + cl]

__device__ __forceinline__ unsigned long long ffma2(unsigned long long a,
                                                    unsigned long long b,
                                                    unsigned long long c) {
    unsigned long long d;
    asm("fma.rn.f32x2 %0, %1, %2, %3;" : "=l"(d) : "l"(a), "l"(b), "l"(c));
    return d;
}
__device__ __forceinline__ unsigned long long mul2(unsigned long long a,
                                                   unsigned long long b) {
    unsigned long long d;
    asm("mul.rn.f32x2 %0, %1, %2;" : "=l"(d) : "l"(a), "l"(b));
    return d;
}
__device__ __forceinline__ unsigned long long pack2(float lo, float hi) {
    unsigned long long r;
    asm("mov.b64 %0, {%1, %2};" : "=l"(r) : "f"(lo), "f"(hi));
    return r;
}
__device__ __forceinline__ float2 unpack2(unsigned long long v) {
    float2 f;
    asm("mov.b64 {%0, %1}, %2;" : "=f"(f.x), "=f"(f.y) : "l"(v));
    return f;
}
__device__ __forceinline__ float ex2f(float x) {
    float r;
    asm("ex2.approx.f32 %0, %1;" : "=f"(r) : "f"(x));
    return r;
}
__device__ __forceinline__ float rcpf(float x) {
    float r;
    asm("rcp.approx.f32 %0, %1;" : "=f"(r) : "f"(x));
    return r;
}

// Shared memory layout (float offsets).
// Region [0, 14656) holds W (8448) + XS (6208) during the GEMM phase, and is
// reused as the compact k,v buffer KV (96*100 = 9600) after a CTA barrier.
#define OFF_W   0        // 64*132 = 8448   w_s[i*132 + o]
#define OFF_XS  8448     // 64*97  = 6208   xs[i*97 + l]
#define OFF_KV  0        // 96*100 = 9600   kv[l*100 + g*12 + c]  (aliases W/XS)
#define OFF_AQ  14656    // 128
#define OFF_BQ  14784    // 128
#define OFF_AS  14912    // 8
#define OFF_AO  14920    // 64
#define OFF_BO  14984    // 64
#define SMEM_FLOATS 15048
#define SMEM_BYTES (SMEM_FLOATS * 4)

extern "C" __global__ void __launch_bounds__(256, 3)
attn_fused_kernel(const float* __restrict__ x, const float* __restrict__ w_qkv,
                  const float* __restrict__ qg, const float* __restrict__ qb,
                  const float* __restrict__ qm, const float* __restrict__ qv,
                  const float* __restrict__ sg, const float* __restrict__ sb,
                  const float* __restrict__ smn, const float* __restrict__ svr,
                  const float* __restrict__ og, const float* __restrict__ ob,
                  const float* __restrict__ om, const float* __restrict__ ov) {
    extern __shared__ float smem[];
    const int tid  = threadIdx.x;
    const int lane = tid & 31;
    const int w    = tid >> 5;
    const int b    = blockIdx.x;
    const int nt   = b >> 6;
    const int hs   = b & 63;

    // ---- issue x-tile LDGs first (hide DRAM latency behind W/BN work) ----
    float4 xr[6];
    {
        const float* xbase = x + (size_t)nt * 393216 + (size_t)hs * 64;
#pragma unroll
        for (int u = 0; u < 6; u++) {
            int idx = tid + 256 * u;
            int i4 = idx & 15, l = idx >> 4;
            xr[u] = *(const float4*)(xbase + (size_t)l * 4096 + i4 * 4);
        }
    }

    // ---- BN coefficient precompute ----
    if (tid < 128) {
        float a = qg[tid] * rsqrtf(qv[tid] + 1e-5f);
        smem[OFF_AQ + tid] = a;
        smem[OFF_BQ + tid] = qb[tid] - qm[tid] * a;
    }
    if (tid < 64) {
        float a = og[tid] * rsqrtf(ov[tid] + 1e-5f);
        smem[OFF_AO + tid] = a;
        smem[OFF_BO + tid] = ob[tid] - om[tid] * a;
    }
    if (tid < 8) {
        smem[OFF_AS + tid] = sg[tid] * rsqrtf(svr[tid] + 1e-5f);
        (void)sb; (void)smn;  // sim BN bias cancels inside softmax
    }

    // ---- load W transposed: w_s[i*132 + o] = w[o*64 + i] (LDG.128) ----
#pragma unroll
    for (int u = 0; u < 8; u++) {
        int idx4 = tid + 256 * u;            // float4 index
        int o = idx4 >> 4, i0 = (idx4 & 15) * 4;
        float4 v = *(const float4*)(w_qkv + idx4 * 4);
        smem[OFF_W + (i0 + 0) * 132 + o] = v.x;
        smem[OFF_W + (i0 + 1) * 132 + o] = v.y;
        smem[OFF_W + (i0 + 2) * 132 + o] = v.z;
        smem[OFF_W + (i0 + 3) * 132 + o] = v.w;
    }

    // ---- store x tile: xs[i*97 + l] ----
#pragma unroll
    for (int u = 0; u < 6; u++) {
        int idx = tid + 256 * u;
        int i4 = idx & 15, l = idx >> 4;
        float* dst = &smem[OFF_XS + (i4 * 4) * 97 + l];
        dst[0]      = xr[u].x;
        dst[97]     = xr[u].y;
        dst[2 * 97] = xr[u].z;
        dst[3 * 97] = xr[u].w;
    }
    __syncthreads();

    const float sc = smem[OFF_AS + w] * 1.4426950408889634f;  // ag/ln2

    // ---- QKV GEMM + BN, all results kept in registers.
    // warp w owns o in [w*16, w*16+16) == group w's q(4), k(4), v(8).
    unsigned long long qp[2][3];   // q, BN+softmax-scale folded
    unsigned long long kv[6][3];   // k,v with BN applied
    {
        unsigned long long acc[8][3];
#pragma unroll
        for (int p = 0; p < 8; p++)
#pragma unroll
            for (int t = 0; t < 3; t++) acc[p][t] = 0ull;

        const float* ws0 = &smem[OFF_W + w * 16];
        const float* xs0 = &smem[OFF_XS + lane];
#pragma unroll 4
        for (int i = 0; i < 64; i++) {
            unsigned long long xv[3];
#pragma unroll
            for (int t = 0; t < 3; t++) {
                float xf = xs0[i * 97 + 32 * t];
                xv[t] = pack2(xf, xf);
            }
#pragma unroll
            for (int p4 = 0; p4 < 4; p4++) {
                ulonglong2 w4 = *(const ulonglong2*)(ws0 + i * 132 + 4 * p4);
#pragma unroll
                for (int t = 0; t < 3; t++) {
                    acc[2 * p4][t]     = ffma2(w4.x, xv[t], acc[2 * p4][t]);
                    acc[2 * p4 + 1][t] = ffma2(w4.y, xv[t], acc[2 * p4 + 1][t]);
                }
            }
        }
        // q: BN fused with softmax scale (lane owns i = lane+32t)
#pragma unroll
        for (int p = 0; p < 2; p++) {
            int o0 = w * 16 + 2 * p;
            float a0 = smem[OFF_AQ + o0] * sc,     b0 = smem[OFF_BQ + o0] * sc;
            float a1 = smem[OFF_AQ + o0 + 1] * sc, b1 = smem[OFF_BQ + o0 + 1] * sc;
#pragma unroll
            for (int t = 0; t < 3; t++) {
                float2 r = unpack2(acc[p][t]);
                qp[p][t] = pack2(r.x * a0 + b0, r.y * a1 + b1);
            }
        }
        // k,v: BN applied, kept in regs until after the barrier
#pragma unroll
        for (int p = 2; p < 8; p++) {
            int o0 = w * 16 + 2 * p;
            float a0 = smem[OFF_AQ + o0],     b0 = smem[OFF_BQ + o0];
            float a1 = smem[OFF_AQ + o0 + 1], b1 = smem[OFF_BQ + o0 + 1];
#pragma unroll
            for (int t = 0; t < 3; t++) {
                float2 r = unpack2(acc[p][t]);
                kv[p - 2][t] = pack2(r.x * a0 + b0, r.y * a1 + b1);
            }
        }
    }

    // ---- barrier: W/XS are dead everywhere; reuse region as KV buffer ----
    __syncthreads();

    // store k,v compact: kv[l*100 + w*12 + 2p'] (STS.64, ~4-way conflicts)
#pragma unroll
    for (int p = 0; p < 6; p++)
#pragma unroll
        for (int t = 0; t < 3; t++) {
            int l = lane + 32 * t;
            *(unsigned long long*)&smem[OFF_KV + l * 100 + w * 12 + 2 * p] = kv[p][t];
        }
    __syncwarp();  // warp w reads only its own 12 columns (all rows it wrote)

    // ---- attention: warp w == group w, streaming over j (flash-style) ----
    {
        unsigned long long acc_sv[4][3];
#pragma unroll
        for (int cp = 0; cp < 4; cp++)
#pragma unroll
            for (int t = 0; t < 3; t++) acc_sv[cp][t] = 0ull;
        float s0 = 0.f, s1 = 0.f, s2 = 0.f;

        const float* kvbase = &smem[OFF_KV + w * 12];
#pragma unroll 4
        for (int j = 0; j < 96; j++) {
            const float* row = kvbase + j * 100;
            ulonglong2 kk = *(const ulonglong2*)(row);
            ulonglong2 va = *(const ulonglong2*)(row + 4);
            ulonglong2 vb = *(const ulonglong2*)(row + 8);
#pragma unroll
            for (int t = 0; t < 3; t++) {
                unsigned long long a2 =
                    ffma2(qp[1][t], kk.y, mul2(qp[0][t], kk.x));
                float2 f = unpack2(a2);
                float e = ex2f(f.x + f.y);           // exp(ag*qk), no max needed
                if (t == 0) s0 += e; else if (t == 1) s1 += e; else s2 += e;
                unsigned long long ee = pack2(e, e);
                acc_sv[0][t] = ffma2(ee, va.x, acc_sv[0][t]);
                acc_sv[1][t] = ffma2(ee, va.y, acc_sv[1][t]);
                acc_sv[2][t] = ffma2(ee, vb.x, acc_sv[2][t]);
                acc_sv[3][t] = ffma2(ee, vb.y, acc_sv[3][t]);
            }
        }

        // epilogue: normalize, out-BN, write scratch (coalesced over i=cl)
        float rs[3] = {rcpf(s0), rcpf(s1), rcpf(s2)};
        float* scr = &g_scratch[(size_t)b * 6144];
#pragma unroll
        for (int cp = 0; cp < 4; cp++) {
            int d0 = w * 8 + 2 * cp;
            float a0 = smem[OFF_AO + d0],     c0 = smem[OFF_BO + d0];
            float a1 = smem[OFF_AO + d0 + 1], c1 = smem[OFF_BO + d0 + 1];
#pragma unroll
            for (int t = 0; t < 3; t++) {
                float2 r = unpack2(acc_sv[cp][t]);
                int i = lane + 32 * t;
                scr[d0 * 96 + i]       = r.x * rs[t] * a0 + c0;
                scr[(d0 + 1) * 96 + i] = r.y * rs[t] * a1 + c1;
            }
        }
    }
}

// Permute scr[(nt*64+hs)*6144 + d*96 + cl] -> out[((nt*96+cl)*64 + d)*64 + hs]
extern "C" __global__ void __launch_bounds__(256)
attn_transpose_kernel(float* __restrict__ out) {
    __shared__ float tile[64 * 97];
    const int nt = blockIdx.x >> 6;
    const int d  = blockIdx.x & 63;

    const float* src = g_scratch + (size_t)nt * 393216 + (size_t)d * 96;
#pragma unroll
    for (int u = 0; u < 6; u++) {
        int idx = threadIdx.x + 256 * u;
        int h = idx / 24, c4 = idx % 24;
        float4 v = *(const float4*)(src + (size_t)h * 6144 + c4 * 4);
        float* dst = &tile[h * 97 + c4 * 4];
        dst[0] = v.x; dst[1] = v.y; dst[2] = v.z; dst[3] = v.w;
    }
    __syncthreads();

    float* dst = out + (size_t)nt * 393216 + (size_t)d * 64;
#pragma unroll
    for (int u = 0; u < 24; u++) {
        int idx = threadIdx.x + 256 * u;
        int cl = idx >> 6, h = idx & 63;
        dst[(size_t)cl * 4096 + h] = tile[h * 97 + cl];
    }
}

extern "C" void kernel_launch(void* const* d_in, const int* in_sizes, int n_in,
                              void* d_out, int out_size) {
    const float* x   = (const float*)d_in[0];
    const float* wq  = (const float*)d_in[1];
    const float* qg  = (const float*)d_in[2];
    const float* qb  = (const float*)d_in[3];
    const float* qm  = (const float*)d_in[4];
    const float* qv  = (const float*)d_in[5];
    const float* sg  = (const float*)d_in[6];
    const float* sb  = (const float*)d_in[7];
    const float* smn = (const float*)d_in[8];
    const float* svr = (const float*)d_in[9];
    const float* og  = (const float*)d_in[10];
    const float* ob  = (const float*)d_in[11];
    const float* om  = (const float*)d_in[12];
    const float* ov  = (const float*)d_in[13];
    float* out = (float*)d_out;

    cudaFuncSetAttribute(attn_fused_kernel,
                         cudaFuncAttributeMaxDynamicSharedMemorySize, SMEM_BYTES);

    attn_fused_kernel<<<2048, 256, SMEM_BYTES>>>(x, wq, qg, qb, qm, qv, sg, sb,
                                                 smn, svr, og, ob, om, ov);
    attn_transpose_kernel<<<2048, 256>>>(out);
}

// round 5
// speedup vs baseline: 1.0478x; 1.0478x over previous
#include <cuda_runtime.h>
#include <cstdint>

// NT=32, HS=64, WS=64 (K of qkv GEMM), CL=96, OD=128, G=8
// b = nt*64 + hs in [0,2048). Each CTA handles b0=2*bx and b1=b0+1 (same nt).

__device__ __align__(16) float g_scratch[2048 * 64 * 96];  // scr[b*6144 + d*96 + cl]

__device__ __forceinline__ unsigned long long ffma2(unsigned long long a,
                                                    unsigned long long b,
                                                    unsigned long long c) {
    unsigned long long d;
    asm("fma.rn.f32x2 %0, %1, %2, %3;" : "=l"(d) : "l"(a), "l"(b), "l"(c));
    return d;
}
__device__ __forceinline__ unsigned long long mul2(unsigned long long a,
                                                   unsigned long long b) {
    unsigned long long d;
    asm("mul.rn.f32x2 %0, %1, %2;" : "=l"(d) : "l"(a), "l"(b));
    return d;
}
__device__ __forceinline__ unsigned long long pack2(float lo, float hi) {
    unsigned long long r;
    asm("mov.b64 %0, {%1, %2};" : "=l"(r) : "f"(lo), "f"(hi));
    return r;
}
__device__ __forceinline__ float2 unpack2(unsigned long long v) {
    float2 f;
    asm("mov.b64 {%0, %1}, %2;" : "=f"(f.x), "=f"(f.y) : "l"(v));
    return f;
}
__device__ __forceinline__ float ex2f(float x) {
    float r;
    asm("ex2.approx.f32 %0, %1;" : "=f"(r) : "f"(x));
    return r;
}
__device__ __forceinline__ float rcpf(float x) {
    float r;
    asm("rcp.approx.f32 %0, %1;" : "=f"(r) : "f"(x));
    return r;
}

// Shared memory layout (float offsets) — identical to the proven R3 layout.
#define OFF_W   0        // 64*132 = 8448   w_s[i*132 + o]
#define OFF_XS  8448     // 64*97  = 6208   xs[i*97 + l]
#define OFF_QKV 14656    // 96*140 = 13440  qkvs[l*140 + o]  (k,v cols, warp-private)
#define OFF_AQ  28096    // 128
#define OFF_BQ  28224    // 128
#define OFF_AS  28352    // 8
#define OFF_AO  28360    // 64
#define OFF_BO  28424    // 64
#define SMEM_FLOATS 28488
#define SMEM_BYTES (SMEM_FLOATS * 4)

// ---- per-problem phases as inline helpers ----

__device__ __forceinline__ void store_x_tile(float* smem, const float4* xr, int tid) {
#pragma unroll
    for (int u = 0; u < 6; u++) {
        int idx = tid + 256 * u;
        int i4 = idx & 15, l = idx >> 4;
        float* dst = &smem[OFF_XS + (i4 * 4) * 97 + l];
        dst[0]      = xr[u].x;
        dst[97]     = xr[u].y;
        dst[2 * 97] = xr[u].z;
        dst[3 * 97] = xr[u].w;
    }
}

// QKV GEMM + BN; q -> qp regs (scale folded), k/v -> QKV smem region (own cols)
__device__ __forceinline__ void qkv_gemm(float* smem, int w, int lane, float sc,
                                         unsigned long long (&qp)[2][3]) {
    unsigned long long acc[8][3];
#pragma unroll
    for (int p = 0; p < 8; p++)
#pragma unroll
        for (int t = 0; t < 3; t++) acc[p][t] = 0ull;

    const float* ws0 = &smem[OFF_W + w * 16];
    const float* xs0 = &smem[OFF_XS + lane];
#pragma unroll 4
    for (int i = 0; i < 64; i++) {
        unsigned long long xv[3];
#pragma unroll
        for (int t = 0; t < 3; t++) {
            float xf = xs0[i * 97 + 32 * t];
            xv[t] = pack2(xf, xf);
        }
#pragma unroll
        for (int p4 = 0; p4 < 4; p4++) {
            ulonglong2 w4 = *(const ulonglong2*)(ws0 + i * 132 + 4 * p4);
#pragma unroll
            for (int t = 0; t < 3; t++) {
                acc[2 * p4][t]     = ffma2(w4.x, xv[t], acc[2 * p4][t]);
                acc[2 * p4 + 1][t] = ffma2(w4.y, xv[t], acc[2 * p4 + 1][t]);
            }
        }
    }
    // q: BN fused with softmax scale (lane owns i = lane+32t)
#pragma unroll
    for (int p = 0; p < 2; p++) {
        int o0 = w * 16 + 2 * p;
        float a0 = smem[OFF_AQ + o0] * sc,     b0 = smem[OFF_BQ + o0] * sc;
        float a1 = smem[OFF_AQ + o0 + 1] * sc, b1 = smem[OFF_BQ + o0 + 1] * sc;
#pragma unroll
        for (int t = 0; t < 3; t++) {
            float2 r = unpack2(acc[p][t]);
            qp[p][t] = pack2(r.x * a0 + b0, r.y * a1 + b1);
        }
    }
    // k,v: BN, stored transposed qkvs[l*140 + o] (warp-private columns)
#pragma unroll
    for (int p = 2; p < 8; p++) {
        int o0 = w * 16 + 2 * p;
        float a0 = smem[OFF_AQ + o0],     b0 = smem[OFF_BQ + o0];
        float a1 = smem[OFF_AQ + o0 + 1], b1 = smem[OFF_BQ + o0 + 1];
#pragma unroll
        for (int t = 0; t < 3; t++) {
            float2 r = unpack2(acc[p][t]);
            int l = lane + 32 * t;
            *(unsigned long long*)&smem[OFF_QKV + l * 140 + o0] =
                pack2(r.x * a0 + b0, r.y * a1 + b1);
        }
    }
}

// flash-style streaming attention over j + out-BN epilogue to scratch
__device__ __forceinline__ void attention(const float* smem, int w, int lane,
                                          const unsigned long long (&qp)[2][3],
                                          int b) {
    const int col0 = w * 16;

    unsigned long long acc_sv[4][3];
#pragma unroll
    for (int cp = 0; cp < 4; cp++)
#pragma unroll
        for (int t = 0; t < 3; t++) acc_sv[cp][t] = 0ull;
    float s0 = 0.f, s1 = 0.f, s2 = 0.f;

#pragma unroll 4
    for (int j = 0; j < 96; j++) {
        const float* row = &smem[OFF_QKV + j * 140 + col0];
        ulonglong2 kk = *(const ulonglong2*)(row + 4);
        ulonglong2 va = *(const ulonglong2*)(row + 8);
        ulonglong2 vb = *(const ulonglong2*)(row + 12);
#pragma unroll
        for (int t = 0; t < 3; t++) {
            unsigned long long a2 = ffma2(qp[1][t], kk.y, mul2(qp[0][t], kk.x));
            float2 f = unpack2(a2);
            float e = ex2f(f.x + f.y);           // exp(ag*qk), no max needed
            if (t == 0) s0 += e; else if (t == 1) s1 += e; else s2 += e;
            unsigned long long ee = pack2(e, e);
            acc_sv[0][t] = ffma2(ee, va.x, acc_sv[0][t]);
            acc_sv[1][t] = ffma2(ee, va.y, acc_sv[1][t]);
            acc_sv[2][t] = ffma2(ee, vb.x, acc_sv[2][t]);
            acc_sv[3][t] = ffma2(ee, vb.y, acc_sv[3][t]);
        }
    }

    float rs[3] = {rcpf(s0), rcpf(s1), rcpf(s2)};
    float* scr = &g_scratch[(size_t)b * 6144];
#pragma unroll
    for (int cp = 0; cp < 4; cp++) {
        int d0 = w * 8 + 2 * cp;
        float a0 = smem[OFF_AO + d0],     c0 = smem[OFF_BO + d0];
        float a1 = smem[OFF_AO + d0 + 1], c1 = smem[OFF_BO + d0 + 1];
#pragma unroll
        for (int t = 0; t < 3; t++) {
            float2 r = unpack2(acc_sv[cp][t]);
            int i = lane + 32 * t;
            scr[d0 * 96 + i]       = r.x * rs[t] * a0 + c0;
            scr[(d0 + 1) * 96 + i] = r.y * rs[t] * a1 + c1;
        }
    }
}

extern "C" __global__ void __launch_bounds__(256, 2)
attn_fused_kernel(const float* __restrict__ x, const float* __restrict__ w_qkv,
                  const float* __restrict__ qg, const float* __restrict__ qb,
                  const float* __restrict__ qm, const float* __restrict__ qv,
                  const float* __restrict__ sg, const float* __restrict__ sb,
                  const float* __restrict__ smn, const float* __restrict__ svr,
                  const float* __restrict__ og, const float* __restrict__ ob,
                  const float* __restrict__ om, const float* __restrict__ ov) {
    extern __shared__ float smem[];
    const int tid  = threadIdx.x;
    const int lane = tid & 31;
    const int w    = tid >> 5;
    const int b0   = blockIdx.x * 2;       // even; b1 = b0+1 shares nt
    const int nt   = b0 >> 6;
    const int hs0  = b0 & 63;

    // ---- issue x(b0) LDGs first ----
    float4 xr0[6];
    const float* xnt = x + (size_t)nt * 393216;
    {
        const float* xbase = xnt + (size_t)hs0 * 64;
#pragma unroll
        for (int u = 0; u < 6; u++) {
            int idx = tid + 256 * u;
            int i4 = idx & 15, l = idx >> 4;
            xr0[u] = *(const float4*)(xbase + (size_t)l * 4096 + i4 * 4);
        }
    }

    // ---- BN coefficient precompute ----
    if (tid < 128) {
        float a = qg[tid] * rsqrtf(qv[tid] + 1e-5f);
        smem[OFF_AQ + tid] = a;
        smem[OFF_BQ + tid] = qb[tid] - qm[tid] * a;
    }
    if (tid < 64) {
        float a = og[tid] * rsqrtf(ov[tid] + 1e-5f);
        smem[OFF_AO + tid] = a;
        smem[OFF_BO + tid] = ob[tid] - om[tid] * a;
    }
    if (tid < 8) {
        smem[OFF_AS + tid] = sg[tid] * rsqrtf(svr[tid] + 1e-5f);
        (void)sb; (void)smn;  // sim BN bias cancels inside softmax
    }

    // ---- load W transposed: w_s[i*132 + o] = w[o*64 + i] (LDG.128) ----
#pragma unroll
    for (int u = 0; u < 8; u++) {
        int idx4 = tid + 256 * u;
        int o = idx4 >> 4, i0 = (idx4 & 15) * 4;
        float4 v = *(const float4*)(w_qkv + idx4 * 4);
        smem[OFF_W + (i0 + 0) * 132 + o] = v.x;
        smem[OFF_W + (i0 + 1) * 132 + o] = v.y;
        smem[OFF_W + (i0 + 2) * 132 + o] = v.z;
        smem[OFF_W + (i0 + 3) * 132 + o] = v.w;
    }

    store_x_tile(smem, xr0, tid);
    __syncthreads();

    // ---- prefetch x(b1): LDGs in flight through the whole GEMM0 ----
    float4 xr1[6];
    {
        const float* xbase = xnt + (size_t)(hs0 + 1) * 64;
#pragma unroll
        for (int u = 0; u < 6; u++) {
            int idx = tid + 256 * u;
            int i4 = idx & 15, l = idx >> 4;
            xr1[u] = *(const float4*)(xbase + (size_t)l * 4096 + i4 * 4);
        }
    }

    const float sc = smem[OFF_AS + w] * 1.4426950408889634f;  // ag/ln2

    // ---- problem b0: GEMM ----
    unsigned long long qp[2][3];
    qkv_gemm(smem, w, lane, sc, qp);
    __syncthreads();            // everyone done reading XS (and writing own kv)

    // ---- swap in x(b1); XS is dead for GEMM0 now ----
    store_x_tile(smem, xr1, tid);
    __syncthreads();            // XS(b1) visible to all before GEMM1

    // ---- attention b0 (reads only this warp's kv columns + qp regs) ----
    attention(smem, w, lane, qp, b0);
    __syncwarp();

    // ---- problem b1: GEMM overwrites this warp's own kv columns ----
    qkv_gemm(smem, w, lane, sc, qp);
    __syncwarp();               // warp-private columns: warp-local ordering suffices

    attention(smem, w, lane, qp, b0 + 1);
}

// Permute scr[(nt*64+hs)*6144 + d*96 + cl] -> out[((nt*96+cl)*64 + d)*64 + hs]
extern "C" __global__ void __launch_bounds__(256)
attn_transpose_kernel(float* __restrict__ out) {
    __shared__ float tile[64 * 97];
    const int nt = blockIdx.x >> 6;
    const int d  = blockIdx.x & 63;

    const float* src = g_scratch + (size_t)nt * 393216 + (size_t)d * 96;
#pragma unroll
    for (int u = 0; u < 6; u++) {
        int idx = threadIdx.x + 256 * u;
        int h = idx / 24, c4 = idx % 24;
        float4 v = *(const float4*)(src + (size_t)h * 6144 + c4 * 4);
        float* dst = &tile[h * 97 + c4 * 4];
        dst[0] = v.x; dst[1] = v.y; dst[2] = v.z; dst[3] = v.w;
    }
    __syncthreads();

    float* dst = out + (size_t)nt * 393216 + (size_t)d * 64;
#pragma unroll
    for (int u = 0; u < 24; u++) {
        int idx = threadIdx.x + 256 * u;
        int cl = idx >> 6, h = idx & 63;
        dst[(size_t)cl * 4096 + h] = tile[h * 97 + cl];
    }
}

extern "C" void kernel_launch(void* const* d_in, const int* in_sizes, int n_in,
                              void* d_out, int out_size) {
    const float* x   = (const float*)d_in[0];
    const float* wq  = (const float*)d_in[1];
    const float* qg  = (const float*)d_in[2];
    const float* qb  = (const float*)d_in[3];
    const float* qm  = (const float*)d_in[4];
    const float* qv  = (const float*)d_in[5];
    const float* sg  = (const float*)d_in[6];
    const float* sb  = (const float*)d_in[7];
    const float* smn = (const float*)d_in[8];
    const float* svr = (const float*)d_in[9];
    const float* og  = (const float*)d_in[10];
    const float* ob  = (const float*)d_in[11];
    const float* om  = (const float*)d_in[12];
    const float* ov  = (const float*)d_in[13];
    float* out = (float*)d_out;

    cudaFuncSetAttribute(attn_fused_kernel,
                         cudaFuncAttributeMaxDynamicSharedMemorySize, SMEM_BYTES);

    attn_fused_kernel<<<1024, 256, SMEM_BYTES>>>(x, wq, qg, qb, qm, qv, sg, sb,
                                                 smn, svr, og, ob, om, ov);
    attn_transpose_kernel<<<2048, 256>>>(out);
}

// round 8
// speedup vs baseline: 1.4473x; 1.3812x over previous
#include <cuda_runtime.h>
#include <cuda_bf16.h>
#include <cstdint>

// NT=32, HS=64, WS=64 (K), CL=96 (l/j), OD=128 (o), G=8
// b = nt*64 + hs in [0,2048). One problem per CTA.

__device__ __align__(16) float g_scratch[2048 * 64 * 96];  // scr[b*6144 + d*96 + cl]

__device__ __forceinline__ unsigned long long ffma2(unsigned long long a,
                                                    unsigned long long b,
                                                    unsigned long long c) {
    unsigned long long d;
    asm("fma.rn.f32x2 %0, %1, %2, %3;" : "=l"(d) : "l"(a), "l"(b), "l"(c));
    return d;
}
__device__ __forceinline__ unsigned long long mul2(unsigned long long a,
                                                   unsigned long long b) {
    unsigned long long d;
    asm("mul.rn.f32x2 %0, %1, %2;" : "=l"(d) : "l"(a), "l"(b));
    return d;
}
__device__ __forceinline__ unsigned long long pack2(float lo, float hi) {
    unsigned long long r;
    asm("mov.b64 %0, {%1, %2};" : "=l"(r) : "f"(lo), "f"(hi));
    return r;
}
__device__ __forceinline__ float2 unpack2(unsigned long long v) {
    float2 f;
    asm("mov.b64 {%0, %1}, %2;" : "=f"(f.x), "=f"(f.y) : "l"(v));
    return f;
}
__device__ __forceinline__ float ex2f(float x) {
    float r;
    asm("ex2.approx.f32 %0, %1;" : "=f"(r) : "f"(x));
    return r;
}
__device__ __forceinline__ float rcpf(float x) {
    float r;
    asm("rcp.approx.f32 %0, %1;" : "=f"(r) : "f"(x));
    return r;
}

__device__ __forceinline__ void mma_bf16(float* d, const uint32_t* a,
                                         uint32_t b0, uint32_t b1) {
    asm volatile(
        "mma.sync.aligned.m16n8k16.row.col.f32.bf16.bf16.f32 "
        "{%0,%1,%2,%3}, {%4,%5,%6,%7}, {%8,%9}, {%0,%1,%2,%3};"
        : "+f"(d[0]), "+f"(d[1]), "+f"(d[2]), "+f"(d[3])
        : "r"(a[0]), "r"(a[1]), "r"(a[2]), "r"(a[3]), "r"(b0), "r"(b1));
}

// split float4 into bf16-high / bf16-low, store 8B to each buffer
__device__ __forceinline__ void split8(char* hb, char* lb, uint32_t off, float4 v) {
    __nv_bfloat162 h0 = __float22bfloat162_rn(make_float2(v.x, v.y));
    __nv_bfloat162 h1 = __float22bfloat162_rn(make_float2(v.z, v.w));
    float2 f0 = __bfloat1622float2(h0), f1 = __bfloat1622float2(h1);
    __nv_bfloat162 l0 = __float22bfloat162_rn(make_float2(v.x - f0.x, v.y - f0.y));
    __nv_bfloat162 l1 = __float22bfloat162_rn(make_float2(v.z - f1.x, v.w - f1.y));
    uint2 hv, lv;
    hv.x = *(uint32_t*)&h0; hv.y = *(uint32_t*)&h1;
    lv.x = *(uint32_t*)&l0; lv.y = *(uint32_t*)&l1;
    *(uint2*)(hb + off) = hv;
    *(uint2*)(lb + off) = lv;
}

// ---------------- shared memory layout ----------------
// Operand buffers (bytes; rows stride 144B). Dead after the MMA barrier;
// qkvs (float qkvs[l*140+o], 53760B) aliases them.
#define OFF_AH 0        // Wh: 128 x 144B
#define OFF_AL 18432    // Wl
#define OFF_XH 36864    // Xh: 96 x 144B
#define OFF_XL 50688    // Xl              (end 64512)
// coefficients, float indices from smem base (beyond byte 64512):
#define CAQ 16128
#define CBQ 16256
#define CAS 16384
#define CAO 16392
#define CBO 16456
#define SMEM_BYTES 66080

extern "C" __global__ void __launch_bounds__(256, 2)
attn_fused_kernel(const float* __restrict__ x, const float* __restrict__ w_qkv,
                  const float* __restrict__ qg, const float* __restrict__ qb,
                  const float* __restrict__ qm, const float* __restrict__ qv,
                  const float* __restrict__ sg, const float* __restrict__ sb,
                  const float* __restrict__ smn, const float* __restrict__ svr,
                  const float* __restrict__ og, const float* __restrict__ ob,
                  const float* __restrict__ om, const float* __restrict__ ov) {
    extern __shared__ __align__(16) char smemc[];
    float* smem = (float*)smemc;
    const int tid  = threadIdx.x;
    const int lane = tid & 31;
    const int w    = tid >> 5;
    const int b    = blockIdx.x;
    const int nt   = b >> 6;
    const int hs   = b & 63;

    // ---- BN coefficient precompute ----
    if (tid < 128) {
        float a = qg[tid] * rsqrtf(qv[tid] + 1e-5f);
        smem[CAQ + tid] = a;
        smem[CBQ + tid] = qb[tid] - qm[tid] * a;
    }
    if (tid < 64) {
        float a = og[tid] * rsqrtf(ov[tid] + 1e-5f);
        smem[CAO + tid] = a;
        smem[CBO + tid] = ob[tid] - om[tid] * a;
    }
    if (tid < 8) {
        smem[CAS + tid] = sg[tid] * rsqrtf(svr[tid] + 1e-5f);
        (void)sb; (void)smn;  // sim BN bias cancels inside softmax
    }

    // ---- operand prep: W split (A, 128 rows(o) x 64 bf16(i)) ----
#pragma unroll
    for (int u = 0; u < 8; u++) {
        int idx4 = tid + 256 * u;
        int o = idx4 >> 4, i4 = idx4 & 15;
        float4 v = *(const float4*)(w_qkv + idx4 * 4);
        split8(smemc + OFF_AH, smemc + OFF_AL, o * 144 + i4 * 8, v);
    }
    // ---- operand prep: X split (B, 96 rows(l) x 64 bf16(i)) ----
    {
        const float* xbase = x + (size_t)nt * 393216 + (size_t)hs * 64;
#pragma unroll
        for (int u = 0; u < 6; u++) {
            int idx = tid + 256 * u;
            int i4 = idx & 15, l = idx >> 4;
            float4 v = *(const float4*)(xbase + (size_t)l * 4096 + i4 * 4);
            split8(smemc + OFF_XH, smemc + OFF_XL, l * 144 + i4 * 8, v);
        }
    }
    __syncthreads();

    // ---- tensor-core QKV GEMM: warp w owns rows o in [16w, 16w+16) ----
    // Fragments built by direct per-lane LDS per the mma.m16n8k16 spec:
    //   A: a0=(row=lane/4,      k=2*(lane%4)), a1=row+8, a2=k+8, a3=both
    //   B: b0=(k=2*(lane%4), n=lane/4), b1=k+8
    float d[12][4];
#pragma unroll
    for (int p = 0; p < 12; p++)
#pragma unroll
        for (int q = 0; q < 4; q++) d[p][q] = 0.f;
    {
        const int qrow = lane >> 2;        // 0..7
        const int qk2  = (lane & 3) * 4;   // byte offset of k-pair: 2*(lane%4)*2

        uint32_t ah[4][4];
#pragma unroll
        for (int k = 0; k < 4; k++) {
            uint32_t off = (uint32_t)(16 * w + qrow) * 144 + 32 * k + qk2;
            ah[k][0] = *(const uint32_t*)(smemc + OFF_AH + off);
            ah[k][1] = *(const uint32_t*)(smemc + OFF_AH + off + 8 * 144);
            ah[k][2] = *(const uint32_t*)(smemc + OFF_AH + off + 16);
            ah[k][3] = *(const uint32_t*)(smemc + OFF_AH + off + 8 * 144 + 16);
        }

        // pass 1: Ah * Xh
#pragma unroll
        for (int k = 0; k < 4; k++)
#pragma unroll
            for (int p = 0; p < 6; p++) {
                uint32_t boff = (uint32_t)(16 * p + qrow) * 144 + 32 * k + qk2;
                uint32_t b0 = *(const uint32_t*)(smemc + OFF_XH + boff);
                uint32_t b1 = *(const uint32_t*)(smemc + OFF_XH + boff + 16);
                uint32_t b2 = *(const uint32_t*)(smemc + OFF_XH + boff + 8 * 144);
                uint32_t b3 = *(const uint32_t*)(smemc + OFF_XH + boff + 8 * 144 + 16);
                mma_bf16(d[2 * p],     ah[k], b0, b1);
                mma_bf16(d[2 * p + 1], ah[k], b2, b3);
            }
        // pass 2: Ah * Xl
#pragma unroll
        for (int k = 0; k < 4; k++)
#pragma unroll
            for (int p = 0; p < 6; p++) {
                uint32_t boff = (uint32_t)(16 * p + qrow) * 144 + 32 * k + qk2;
                uint32_t b0 = *(const uint32_t*)(smemc + OFF_XL + boff);
                uint32_t b1 = *(const uint32_t*)(smemc + OFF_XL + boff + 16);
                uint32_t b2 = *(const uint32_t*)(smemc + OFF_XL + boff + 8 * 144);
                uint32_t b3 = *(const uint32_t*)(smemc + OFF_XL + boff + 8 * 144 + 16);
                mma_bf16(d[2 * p],     ah[k], b0, b1);
                mma_bf16(d[2 * p + 1], ah[k], b2, b3);
            }
        // pass 3: Al * Xh (Al loaded here to shorten live range)
#pragma unroll
        for (int k = 0; k < 4; k++) {
            uint32_t off = (uint32_t)(16 * w + qrow) * 144 + 32 * k + qk2;
            uint32_t al[4];
            al[0] = *(const uint32_t*)(smemc + OFF_AL + off);
            al[1] = *(const uint32_t*)(smemc + OFF_AL + off + 8 * 144);
            al[2] = *(const uint32_t*)(smemc + OFF_AL + off + 16);
            al[3] = *(const uint32_t*)(smemc + OFF_AL + off + 8 * 144 + 16);
#pragma unroll
            for (int p = 0; p < 6; p++) {
                uint32_t boff = (uint32_t)(16 * p + qrow) * 144 + 32 * k + qk2;
                uint32_t b0 = *(const uint32_t*)(smemc + OFF_XH + boff);
                uint32_t b1 = *(const uint32_t*)(smemc + OFF_XH + boff + 16);
                uint32_t b2 = *(const uint32_t*)(smemc + OFF_XH + boff + 8 * 144);
                uint32_t b3 = *(const uint32_t*)(smemc + OFF_XH + boff + 8 * 144 + 16);
                mma_bf16(d[2 * p],     al, b0, b1);
                mma_bf16(d[2 * p + 1], al, b2, b3);
            }
        }
    }
    __syncthreads();   // all operand reads done; safe to overwrite with qkvs

    // ---- epilogue: BN + store fragments to qkvs[l*140 + o] (own columns) ----
    {
        int r0 = 16 * w + (lane >> 2);
        float aq0 = smem[CAQ + r0],     bq0 = smem[CBQ + r0];
        float aq8 = smem[CAQ + r0 + 8], bq8 = smem[CBQ + r0 + 8];
#pragma unroll
        for (int p = 0; p < 12; p++) {
            int c = 8 * p + 2 * (lane & 3);
            smem[c * 140 + r0]             = d[p][0] * aq0 + bq0;
            smem[(c + 1) * 140 + r0]       = d[p][1] * aq0 + bq0;
            smem[c * 140 + r0 + 8]         = d[p][2] * aq8 + bq8;
            smem[(c + 1) * 140 + r0 + 8]   = d[p][3] * aq8 + bq8;
        }
    }
    __syncwarp();   // warp-private columns

    // ---- attention: warp w == group w, flash-style streaming over j ----
    {
        const int col0 = w * 16;
        const float sc = smem[CAS + w] * 1.4426950408889634f;  // ag/ln2
        const unsigned long long sc2 = pack2(sc, sc);

        unsigned long long qp[2][3];
#pragma unroll
        for (int cp = 0; cp < 2; cp++)
#pragma unroll
            for (int t = 0; t < 3; t++) {
                unsigned long long qraw = *(const unsigned long long*)
                    &smem[(lane + 32 * t) * 140 + col0 + 2 * cp];
                qp[cp][t] = mul2(qraw, sc2);
            }

        unsigned long long acc_sv[4][3];
#pragma unroll
        for (int cp = 0; cp < 4; cp++)
#pragma unroll
            for (int t = 0; t < 3; t++) acc_sv[cp][t] = 0ull;
        float s0 = 0.f, s1 = 0.f, s2 = 0.f;

#pragma unroll 4
        for (int j = 0; j < 96; j++) {
            const float* row = &smem[j * 140 + col0];
            ulonglong2 kk = *(const ulonglong2*)(row + 4);
            ulonglong2 va = *(const ulonglong2*)(row + 8);
            ulonglong2 vb = *(const ulonglong2*)(row + 12);
#pragma unroll
            for (int t = 0; t < 3; t++) {
                unsigned long long a2 = ffma2(qp[1][t], kk.y, mul2(qp[0][t], kk.x));
                float2 f = unpack2(a2);
                float e = ex2f(f.x + f.y);          // exp(ag*qk), no max needed
                if (t == 0) s0 += e; else if (t == 1) s1 += e; else s2 += e;
                unsigned long long ee = pack2(e, e);
                acc_sv[0][t] = ffma2(ee, va.x, acc_sv[0][t]);
                acc_sv[1][t] = ffma2(ee, va.y, acc_sv[1][t]);
                acc_sv[2][t] = ffma2(ee, vb.x, acc_sv[2][t]);
                acc_sv[3][t] = ffma2(ee, vb.y, acc_sv[3][t]);
            }
        }

        float rs[3] = {rcpf(s0), rcpf(s1), rcpf(s2)};
        float* scr = &g_scratch[(size_t)b * 6144];
#pragma unroll
        for (int cp = 0; cp < 4; cp++) {
            int d0 = w * 8 + 2 * cp;
            float a0 = smem[CAO + d0],     c0f = smem[CBO + d0];
            float a1 = smem[CAO + d0 + 1], c1f = smem[CBO + d0 + 1];
#pragma unroll
            for (int t = 0; t < 3; t++) {
                float2 r = unpack2(acc_sv[cp][t]);
                int i = lane + 32 * t;
                scr[d0 * 96 + i]       = r.x * rs[t] * a0 + c0f;
                scr[(d0 + 1) * 96 + i] = r.y * rs[t] * a1 + c1f;
            }
        }
    }
}

// Permute scr[(nt*64+hs)*6144 + d*96 + cl] -> out[((nt*96+cl)*64 + d)*64 + hs]
extern "C" __global__ void __launch_bounds__(256)
attn_transpose_kernel(float* __restrict__ out) {
    __shared__ float tile[64 * 97];
    const int nt = blockIdx.x >> 6;
    const int d  = blockIdx.x & 63;

    const float* src = g_scratch + (size_t)nt * 393216 + (size_t)d * 96;
#pragma unroll
    for (int u = 0; u < 6; u++) {
        int idx = threadIdx.x + 256 * u;
        int h = idx / 24, c4 = idx % 24;
        float4 v = *(const float4*)(src + (size_t)h * 6144 + c4 * 4);
        float* dst = &tile[h * 97 + c4 * 4];
        dst[0] = v.x; dst[1] = v.y; dst[2] = v.z; dst[3] = v.w;
    }
    __syncthreads();

    float* dst = out + (size_t)nt * 393216 + (size_t)d * 64;
#pragma unroll
    for (int u = 0; u < 24; u++) {
        int idx = threadIdx.x + 256 * u;
        int cl = idx >> 6, h = idx & 63;
        dst[(size_t)cl * 4096 + h] = tile[h * 97 + cl];
    }
}

extern "C" void kernel_launch(void* const* d_in, const int* in_sizes, int n_in,
                              void* d_out, int out_size) {
    const float* x   = (const float*)d_in[0];
    const float* wq  = (const float*)d_in[1];
    const float* qg  = (const float*)d_in[2];
    const float* qb  = (const float*)d_in[3];
    const float* qm  = (const float*)d_in[4];
    const float* qv  = (const float*)d_in[5];
    const float* sg  = (const float*)d_in[6];
    const float* sb  = (const float*)d_in[7];
    const float* smn = (const float*)d_in[8];
    const float* svr = (const float*)d_in[9];
    const float* og  = (const float*)d_in[10];
    const float* ob  = (const float*)d_in[11];
    const float* om  = (const float*)d_in[12];
    const float* ov  = (const float*)d_in[13];
    float* out = (float*)d_out;

    cudaFuncSetAttribute(attn_fused_kernel,
                         cudaFuncAttributeMaxDynamicSharedMemorySize, SMEM_BYTES);

    attn_fused_kernel<<<2048, 256, SMEM_BYTES>>>(x, wq, qg, qb, qm, qv, sg, sb,
                                                 smn, svr, og, ob, om, ov);
    attn_transpose_kernel<<<2048, 256>>>(out);
}